// round 5
// baseline (speedup 1.0000x reference)
#include <cuda_runtime.h>

#define BB 128
#define GG 20000
#define NELEM (BB * GG)        // 2,560,000
#define NPAIR (NELEM / 2)      // 1,280,000
#define HID 64
#define KB 9                   // NUM_BINS - 1
#define NSEG (HID + 1)         // 65 piecewise-linear segments
#define ACROW 10               // padded row: 10 float2 = 80B, 16B-aligned rows
#define NTAB 4096              // bucket table entries (top 12 bits of monotone key)

// Piecewise-linear representation of logits(x): segment s -> logit_k = A*x + C
__device__ float         g_T[HID];             // sorted breakpoints
__device__ float2        g_AC[NSEG * ACROW];   // (A, C) pairs, padded rows
__device__ unsigned char g_Tab[NTAB];          // lower-bound-at-bucket-start table

__device__ __forceinline__ unsigned int mono_key(float x) {
    unsigned int u = __float_as_uint(x);
    return ((int)u < 0) ? ~u : (u | 0x80000000u);
}

// ---------------------------------------------------------------------------
// Precompute kernel: 1 block, 640 threads.
// ---------------------------------------------------------------------------
__global__ void precompute_kernel(const float* __restrict__ W1,
                                  const float* __restrict__ b1,
                                  const float* __restrict__ W2,
                                  const float* __restrict__ b2) {
    __shared__ float w1s[HID], b1s[HID], W2s[HID * KB], b2s[KB];
    __shared__ float t[HID], srt[HID];
    __shared__ unsigned int ku[HID];
    int tid = threadIdx.x;

    if (tid < HID)      { w1s[tid] = W1[tid]; b1s[tid] = b1[tid]; }
    if (tid < HID * KB) { W2s[tid] = W2[tid]; }
    if (tid < KB)       { b2s[tid] = b2[tid]; }
    __syncthreads();

    // breakpoints t_j = -b1_j / w1_j (clamped; w==0 -> sentinel)
    if (tid < HID) {
        float w = w1s[tid], b = b1s[tid];
        float tv = (w != 0.0f) ? (-b / w) : 1e30f;
        if (!(tv > -1e30f)) tv = -1e30f;
        if (tv > 1e30f)     tv = 1e30f;
        t[tid] = tv;
    }
    __syncthreads();

    // rank sort (64 elements)
    if (tid < HID) {
        float tv = t[tid];
        int rank = 0;
        #pragma unroll 8
        for (int i = 0; i < HID; i++) {
            float o = t[i];
            rank += (o < tv || (o == tv && i < tid)) ? 1 : 0;
        }
        srt[rank] = tv;
    }
    __syncthreads();

    if (tid < HID) { g_T[tid] = srt[tid]; ku[tid] = mono_key(srt[tid]); }

    // Per-(segment, bin) coefficients
    if (tid < NSEG * KB) {
        int s = tid / KB;
        int k = tid - s * KB;
        float xm;
        if (s == 0)        xm = srt[0] - 1.0f;
        else if (s == HID) xm = srt[HID - 1] + 1.0f;
        else               xm = 0.5f * srt[s - 1] + 0.5f * srt[s];

        float A = 0.0f, C = b2s[k];
        #pragma unroll 4
        for (int j = 0; j < HID; j++) {
            float w = w1s[j], b = b1s[j];
            float h = fmaf(xm, w, b);
            float c = (h >= 0.0f) ? 1.0f : 0.01f;
            float wv = W2s[j * KB + k];
            A = fmaf(c * w, wv, A);
            C = fmaf(c * b, wv, C);
        }
        g_AC[s * ACROW + k] = make_float2(A, C);
    }
    __syncthreads();

    // Bucket table: g_Tab[i] = #(breakpoints with key < (i<<20))
    for (int i = tid; i < NTAB; i += 640) {
        unsigned int bkey = (unsigned int)i << 20;
        int cnt = 0;
        #pragma unroll 8
        for (int j = 0; j < HID; j++) cnt += (ku[j] < bkey) ? 1 : 0;
        g_Tab[i] = (unsigned char)cnt;
    }
}

// ---------------------------------------------------------------------------
// Main kernel: 256 threads/block, one element PAIR per thread, SMEM-staged
// coalesced output.
// ---------------------------------------------------------------------------
__device__ __forceinline__ void process_one(float x,
                                            const float* __restrict__ sT,
                                            const float2* __restrict__ sAC,
                                            const unsigned char* __restrict__ sTab,
                                            float* o /*10*/, float& mask) {
    // bucket lookup + short exact refinement
    int pos = sTab[mono_key(x) >> 20];
    while (pos < HID && sT[pos] < x) pos++;

    const float2* row = sAC + pos * ACROW;
    float4 r0 = *reinterpret_cast<const float4*>(row);
    float4 r1 = *reinterpret_cast<const float4*>(row + 2);
    float4 r2 = *reinterpret_cast<const float4*>(row + 4);
    float4 r3 = *reinterpret_cast<const float4*>(row + 6);
    float2 r4 = row[8];

    // logits bounded (|A*x+C| ~ 10), no max-subtraction needed
    float e0 = __expf(fmaf(r0.x, x, r0.y));
    float e1 = __expf(fmaf(r0.z, x, r0.w));
    float e2 = __expf(fmaf(r1.x, x, r1.y));
    float e3 = __expf(fmaf(r1.z, x, r1.w));
    float e4 = __expf(fmaf(r2.x, x, r2.y));
    float e5 = __expf(fmaf(r2.z, x, r2.w));
    float e6 = __expf(fmaf(r3.x, x, r3.y));
    float e7 = __expf(fmaf(r3.z, x, r3.w));
    float e8 = __expf(fmaf(r4.x, x, r4.y));

    float s = (((e0 + e1) + (e2 + e3)) + ((e4 + e5) + (e6 + e7))) + e8;
    float m = (x != 0.0f) ? 1.0f : 0.0f;
    float invm = __fdividef(m, s);

    mask = m;
    o[0] = 1.0f - m;
    o[1] = e0 * invm;  o[2] = e1 * invm;  o[3] = e2 * invm;
    o[4] = e3 * invm;  o[5] = e4 * invm;  o[6] = e5 * invm;
    o[7] = e6 * invm;  o[8] = e7 * invm;  o[9] = e8 * invm;
}

__global__ void __launch_bounds__(256) expr_quant_kernel(const float* __restrict__ expr,
                                                         float* __restrict__ out) {
    __shared__ float         sT[HID];
    __shared__ float2        sAC[NSEG * ACROW];
    __shared__ unsigned char sTab[NTAB];
    __shared__ float4        stage[256 * 5];   // 20 KB output staging

    int tid = threadIdx.x;
    if (tid < HID) sT[tid] = g_T[tid];
    for (int i = tid; i < NSEG * ACROW; i += 256) sAC[i] = g_AC[i];
    {
        const uchar4* src = reinterpret_cast<const uchar4*>(g_Tab);
        uchar4* dst = reinterpret_cast<uchar4*>(sTab);
        for (int i = tid; i < NTAB / 4; i += 256) dst[i] = src[i];
    }
    __syncthreads();

    size_t pairBase = (size_t)blockIdx.x * 256;
    size_t pair = pairBase + tid;

    float2 xv = *reinterpret_cast<const float2*>(expr + 2 * pair);

    float o[20];
    float m0, m1;
    process_one(xv.x, sT, sAC, sTab, o,      m0);
    process_one(xv.y, sT, sAC, sTab, o + 10, m1);

    // stage 5 float4s per thread (output-layout order)
    float4* st = stage + tid * 5;
    st[0] = make_float4(o[0],  o[1],  o[2],  o[3]);
    st[1] = make_float4(o[4],  o[5],  o[6],  o[7]);
    st[2] = make_float4(o[8],  o[9],  o[10], o[11]);
    st[3] = make_float4(o[12], o[13], o[14], o[15]);
    st[4] = make_float4(o[16], o[17], o[18], o[19]);

    // mask store is already coalesced (8B/lane, contiguous)
    *reinterpret_cast<float2*>(out + (size_t)NELEM * 10 + 2 * pair) = make_float2(m0, m1);

    __syncthreads();

    // block-linear coalesced copy-out: each STG.128 covers 512B contiguous/warp
    float4* dst = reinterpret_cast<float4*>(out + pairBase * 20);
    #pragma unroll
    for (int m = 0; m < 5; m++)
        dst[tid + 256 * m] = stage[tid + 256 * m];
}

// ---------------------------------------------------------------------------
extern "C" void kernel_launch(void* const* d_in, const int* in_sizes, int n_in,
                              void* d_out, int out_size) {
    const float* expr = (const float*)d_in[0];
    const float* W1   = (const float*)d_in[1];
    const float* b1   = (const float*)d_in[2];
    const float* W2   = (const float*)d_in[3];
    const float* b2   = (const float*)d_in[4];
    float* out = (float*)d_out;

    precompute_kernel<<<1, 640>>>(W1, b1, W2, b2);
    expr_quant_kernel<<<NPAIR / 256, 256>>>(expr, out);
}

// round 6
// speedup vs baseline: 1.0056x; 1.0056x over previous
#include <cuda_runtime.h>

#define BB 128
#define GG 20000
#define NELEM (BB * GG)        // 2,560,000
#define NPAIR (NELEM / 2)      // 1,280,000
#define HID 64
#define KB 9                   // NUM_BINS - 1
#define NSEG (HID + 1)         // 65 piecewise-linear segments
#define ACROW 10               // padded row: 10 float2 = 80B
#define LOG2E 1.44269504088896340736f

// Piecewise-linear representation: segment s -> logit_k*log2e = A*x + C
__device__ float  g_T[HID];            // sorted breakpoints
__device__ float2 g_AC[NSEG * ACROW];  // (A, C), pre-scaled by log2(e)

__device__ __forceinline__ float ex2(float v) {
    float r;
    asm("ex2.approx.f32 %0, %1;" : "=f"(r) : "f"(v));
    return r;
}

// ---------------------------------------------------------------------------
// Precompute kernel: 1 block, 640 threads. (No bucket table this round.)
// ---------------------------------------------------------------------------
__global__ void precompute_kernel(const float* __restrict__ W1,
                                  const float* __restrict__ b1,
                                  const float* __restrict__ W2,
                                  const float* __restrict__ b2) {
    __shared__ float w1s[HID], b1s[HID], W2s[HID * KB], b2s[KB];
    __shared__ float t[HID], srt[HID];
    int tid = threadIdx.x;

    if (tid < HID)      { w1s[tid] = W1[tid]; b1s[tid] = b1[tid]; }
    if (tid < HID * KB) { W2s[tid] = W2[tid]; }
    if (tid < KB)       { b2s[tid] = b2[tid]; }
    __syncthreads();

    if (tid < HID) {
        float w = w1s[tid], b = b1s[tid];
        float tv = (w != 0.0f) ? (-b / w) : 1e30f;
        if (!(tv > -1e30f)) tv = -1e30f;
        if (tv > 1e30f)     tv = 1e30f;
        t[tid] = tv;
    }
    __syncthreads();

    if (tid < HID) {   // rank sort
        float tv = t[tid];
        int rank = 0;
        #pragma unroll 8
        for (int i = 0; i < HID; i++) {
            float o = t[i];
            rank += (o < tv || (o == tv && i < tid)) ? 1 : 0;
        }
        srt[rank] = tv;
    }
    __syncthreads();

    if (tid < HID) g_T[tid] = srt[tid];

    if (tid < NSEG * KB) {
        int s = tid / KB;
        int k = tid - s * KB;
        float xm;
        if (s == 0)        xm = srt[0] - 1.0f;
        else if (s == HID) xm = srt[HID - 1] + 1.0f;
        else               xm = 0.5f * srt[s - 1] + 0.5f * srt[s];

        float A = 0.0f, C = b2s[k];
        #pragma unroll 4
        for (int j = 0; j < HID; j++) {
            float w = w1s[j], b = b1s[j];
            float h = fmaf(xm, w, b);
            float c = (h >= 0.0f) ? 1.0f : 0.01f;
            float wv = W2s[j * KB + k];
            A = fmaf(c * w, wv, A);
            C = fmaf(c * b, wv, C);
        }
        g_AC[s * ACROW + k] = make_float2(A * LOG2E, C * LOG2E);
    }
}

// ---------------------------------------------------------------------------
// Main kernel: one pair per thread. Zero elements: predicated constant
// pattern. Nonzero elements: warp-cooperative compacted expensive path
// (ballot + rank-select + shuffle), ~6 active lanes per warp on average.
// ---------------------------------------------------------------------------
__global__ void __launch_bounds__(256) expr_quant_kernel(const float* __restrict__ expr,
                                                         float* __restrict__ out) {
    __shared__ float  sT[HID];
    __shared__ float2 sAC[NSEG * ACROW];
    int tid = threadIdx.x;
    if (tid < HID) sT[tid] = g_T[tid];
    for (int i = tid; i < NSEG * ACROW; i += 256) sAC[i] = g_AC[i];
    __syncthreads();

    size_t pair = (size_t)blockIdx.x * 256 + tid;
    float2 xv = *reinterpret_cast<const float2*>(expr + 2 * pair);
    float x0 = xv.x, x1 = xv.y;

    // mask (always, coalesced 8B/lane)
    float m0 = (x0 != 0.0f) ? 1.0f : 0.0f;
    float m1 = (x1 != 0.0f) ? 1.0f : 0.0f;
    *reinterpret_cast<float2*>(out + (size_t)NELEM * 10 + 2 * pair) = make_float2(m0, m1);

    // zero-pattern stores (predicated; ~90% of elements take these)
    float* p0 = out + pair * 20;          // element 2*pair, 16B-aligned
    if (x0 == 0.0f) {
        *reinterpret_cast<float4*>(p0)     = make_float4(1.f, 0.f, 0.f, 0.f);
        *reinterpret_cast<float4*>(p0 + 4) = make_float4(0.f, 0.f, 0.f, 0.f);
        *reinterpret_cast<float2*>(p0 + 8) = make_float2(0.f, 0.f);
    }
    if (x1 == 0.0f) {
        *reinterpret_cast<float2*>(p0 + 10) = make_float2(1.f, 0.f);
        *reinterpret_cast<float4*>(p0 + 12) = make_float4(0.f, 0.f, 0.f, 0.f);
        *reinterpret_cast<float4*>(p0 + 16) = make_float4(0.f, 0.f, 0.f, 0.f);
    }

    // ---- warp-cooperative fixup over this warp's 64 elements ----
    const unsigned FULL = 0xFFFFFFFFu;
    unsigned bal0 = __ballot_sync(FULL, x0 != 0.0f);
    unsigned bal1 = __ballot_sync(FULL, x1 != 0.0f);
    // bit j<32: even element of lane j; bit 32+j: odd element of lane j
    unsigned long long rem = (unsigned long long)bal0 | ((unsigned long long)bal1 << 32);
    int lane = tid & 31;
    size_t warpElemBase = ((size_t)blockIdx.x * 256 + (size_t)(tid & ~31)) * 2;

    while (rem) {
        unsigned lo = (unsigned)rem, hi = (unsigned)(rem >> 32);
        int clo = __popc(lo);
        int nnz = clo + __popc(hi);

        int idx;
        if (lane < clo) idx = __fns(lo, 0, lane + 1);
        else            idx = 32 + __fns(hi, 0, lane - clo + 1);

        bool act = (lane < nnz);
        int srcLane = idx & 31;                       // benign for inactive lanes
        float xa = __shfl_sync(FULL, x0, srcLane);
        float xb = __shfl_sync(FULL, x1, srcLane);
        float x = (idx < 32) ? xa : xb;

        if (act) {
            // branchless lower_bound: pos = #(T < x)
            int pos = 0;
            #pragma unroll
            for (int step = 32; step >= 1; step >>= 1)
                if (sT[pos + step - 1] < x) pos += step;

            const float2* row = sAC + pos * ACROW;
            float4 r0 = *reinterpret_cast<const float4*>(row);
            float4 r1 = *reinterpret_cast<const float4*>(row + 2);
            float4 r2 = *reinterpret_cast<const float4*>(row + 4);
            float4 r3 = *reinterpret_cast<const float4*>(row + 6);
            float2 r4 = row[8];

            float e0 = ex2(fmaf(r0.x, x, r0.y));
            float e1 = ex2(fmaf(r0.z, x, r0.w));
            float e2 = ex2(fmaf(r1.x, x, r1.y));
            float e3 = ex2(fmaf(r1.z, x, r1.w));
            float e4 = ex2(fmaf(r2.x, x, r2.y));
            float e5 = ex2(fmaf(r2.z, x, r2.w));
            float e6 = ex2(fmaf(r3.x, x, r3.y));
            float e7 = ex2(fmaf(r3.z, x, r3.w));
            float e8 = ex2(fmaf(r4.x, x, r4.y));

            float s = (((e0 + e1) + (e2 + e3)) + ((e4 + e5) + (e6 + e7))) + e8;
            float inv = __fdividef(1.0f, s);

            int elem = (idx < 32) ? (idx * 2) : ((idx - 32) * 2 + 1);
            float* q = out + (warpElemBase + (size_t)elem) * 10;
            *reinterpret_cast<float2*>(q)     = make_float2(0.0f,     e0 * inv);
            *reinterpret_cast<float2*>(q + 2) = make_float2(e1 * inv, e2 * inv);
            *reinterpret_cast<float2*>(q + 4) = make_float2(e3 * inv, e4 * inv);
            *reinterpret_cast<float2*>(q + 6) = make_float2(e5 * inv, e6 * inv);
            *reinterpret_cast<float2*>(q + 8) = make_float2(e7 * inv, e8 * inv);
        }

        if (nnz <= 32) break;
        // clear the 32 processed (lowest) set bits
        int p32 = (clo >= 32) ? __fns(lo, 0, 32) : 32 + __fns(hi, 0, 32 - clo);
        if (p32 >= 63) rem = 0;
        else           rem &= ~((1ull << (p32 + 1)) - 1ull);
    }
}

// ---------------------------------------------------------------------------
extern "C" void kernel_launch(void* const* d_in, const int* in_sizes, int n_in,
                              void* d_out, int out_size) {
    const float* expr = (const float*)d_in[0];
    const float* W1   = (const float*)d_in[1];
    const float* b1   = (const float*)d_in[2];
    const float* W2   = (const float*)d_in[3];
    const float* b2   = (const float*)d_in[4];
    float* out = (float*)d_out;

    precompute_kernel<<<1, 640>>>(W1, b1, W2, b2);
    expr_quant_kernel<<<NPAIR / 256, 256>>>(expr, out);
}